// round 8
// baseline (speedup 1.0000x reference)
#include <cuda_runtime.h>
#include <cuda_bf16.h>
#include <mma.h>
#include <math.h>
#include <stdint.h>

using namespace nvcuda;

#define NTOT 131072
#define DIN 768
#define DH 128
#define DA 32
#define KSEL 64
#define KC 64
#define NITER 12
#define LCAP 4096
#define EQCAP 4096

// ---------------- device scratch (allocation-free) ----------------
__device__ float          g_x[(size_t)NTOT * DH];     // post-activation x rows (64 MB)
__device__ float          g_s[NTOT];                  // attention scores
__device__ float          g_Z;                        // softmax denominator
__device__ int            g_topidx[KSEL];             // top-64 indices, value-desc order
__device__ float          g_zw[KSEL * DA];
__device__ float          g_part[16 * DH];
__device__ float          g_dummy[DH];                // L2-prefetch sink
__device__ __nv_bfloat16  g_Wthi[DH * DIN];           // W1^T hi  [n][k]
__device__ __nv_bfloat16  g_Wtlo[DH * DIN];           // W1^T lo  [n][k]

// ---------------- fused kernel smem map (bytes) ----------------
// mainloop: STA 128 x 68f (272B pitch) = 34816
//           AHI/ALO 128 x 72 bf16 (144B pitch) = 18432 each
//           BHI[2]/BLO[2] 18432 each buf
#define OFF_STA 0
#define OFF_AHI 34816
#define OFF_ALO 53248
#define OFF_BHI 71680
#define OFF_BLO 108544
// epilogue reuse: XS = 16 warps x (16 x 76 f) = 77824 ; W1S 128x32 f = 16384
#define XPITCH 76
#define OFF_XS  0
#define OFF_W1S 77824
#define SM_BYTES 145408

__device__ __forceinline__ uint32_t smem_u32(const void* p) {
    uint32_t a;
    asm("{ .reg .u64 t; cvta.to.shared.u64 t, %1; cvt.u32.u64 %0, t; }" : "=r"(a) : "l"(p));
    return a;
}
__device__ __forceinline__ void cp16(uint32_t s, const void* g) {
    asm volatile("cp.async.cg.shared.global [%0], [%1], 16;" :: "r"(s), "l"(g));
}
__device__ __forceinline__ void cp_commit() { asm volatile("cp.async.commit_group;" ::: "memory"); }
__device__ __forceinline__ void cp_wait0()  { asm volatile("cp.async.wait_group 0;" ::: "memory"); }

// float -> monotone sortable uint
__device__ __forceinline__ unsigned f2k(float f) {
    unsigned u = __float_as_uint(f);
    return u ^ ((u & 0x80000000u) ? 0xFFFFFFFFu : 0x80000000u);
}
// pack two floats' bf16 hi parts and bf16 residual lo parts
__device__ __forceinline__ void split2(float x, float y, uint32_t& hi2, uint32_t& lo2) {
    __nv_bfloat16 hx = __float2bfloat16(x), hy = __float2bfloat16(y);
    float rx = x - __bfloat162float(hx), ry = y - __bfloat162float(hy);
    __nv_bfloat16 lx = __float2bfloat16(rx), ly = __float2bfloat16(ry);
    hi2 = (uint32_t)__bfloat16_as_ushort(hx) | ((uint32_t)__bfloat16_as_ushort(hy) << 16);
    lo2 = (uint32_t)__bfloat16_as_ushort(lx) | ((uint32_t)__bfloat16_as_ushort(ly) << 16);
}

// ---------------- kernel 0: W1 -> transposed bf16 hi/lo, + L2 prefetch of Wz ----------------
__global__ __launch_bounds__(256) void conv_w1(const float* __restrict__ W1,
                                               const float* __restrict__ Wz) {
    int n = blockIdx.x;
    for (int k = threadIdx.x; k < DIN; k += 256) {
        float v = W1[(size_t)k * DH + n];
        __nv_bfloat16 h = __float2bfloat16(v);
        g_Wthi[n * DIN + k] = h;
        g_Wtlo[n * DIN + k] = __float2bfloat16(v - __bfloat162float(h));
    }
    // touch Wz slice: 2048 rows / 128 blocks = 16 rows per block
    float acc = 0.f;
    const float* wzb = Wz + (size_t)n * 16 * DH;
    for (int i = threadIdx.x; i < 16 * DH; i += 256) acc += wzb[i];
    __shared__ float red[8];
    #pragma unroll
    for (int off = 16; off; off >>= 1) acc += __shfl_xor_sync(0xffffffffu, acc, off);
    if ((threadIdx.x & 31) == 0) red[threadIdx.x >> 5] = acc;
    __syncthreads();
    if (threadIdx.x == 0) {
        float t = 0.f;
        for (int i = 0; i < 8; i++) t += red[i];
        g_dummy[n] = t;
    }
}

// ---------------- kernel 1: WMMA bf16-split GEMM + BN/ReLU + h + s ----------------
__global__ __launch_bounds__(512) void fused_main_tc(
    const float* __restrict__ input,
    const float* __restrict__ b1, const float* __restrict__ g1, const float* __restrict__ be1,
    const float* __restrict__ Watt1, const float* __restrict__ batt1,
    const float* __restrict__ g2, const float* __restrict__ be2,
    const float* __restrict__ Watt2, const float* __restrict__ batt2)
{
    extern __shared__ char sm[];
    const uint32_t su = smem_u32(sm);
    float*         staf = (float*)(sm + OFF_STA);
    __nv_bfloat16* sAhi = (__nv_bfloat16*)(sm + OFF_AHI);
    __nv_bfloat16* sAlo = (__nv_bfloat16*)(sm + OFF_ALO);

    const int tid = threadIdx.x;
    const int lane = tid & 31, wid = tid >> 5;
    const int wg = wid >> 3;          // 0/1: N half
    const int w8 = wid & 7;           // 0..7: M group of 16 rows
    const int m0 = blockIdx.x * 128;

    wmma::fragment<wmma::accumulator, 16, 16, 16, float> fc[4];
    #pragma unroll
    for (int j = 0; j < 4; j++) wmma::fill_fragment(fc[j], 0.0f);

    // prologue: issue chunk 0
    {
        #pragma unroll
        for (int j = 0; j < 4; j++) {
            int t = tid + 512 * j;
            int row = t >> 4, c4 = t & 15;
            cp16(su + OFF_STA + row * 272 + c4 * 16, input + (size_t)(m0 + row) * DIN + c4 * 4);
        }
        #pragma unroll
        for (int j = 0; j < 2; j++) {
            int t = tid + 512 * j;
            int row = t >> 3, k8 = (t & 7) << 3;
            cp16(su + OFF_BHI + row * 144 + k8 * 2, g_Wthi + row * DIN + k8);
            cp16(su + OFF_BLO + row * 144 + k8 * 2, g_Wtlo + row * DIN + k8);
        }
        cp_commit();
    }

    const int cvr = tid >> 2, cvc = (tid & 3) << 4;   // convert: 4 thr/row, 16 floats each

    for (int c = 0; c < NITER; c++) {
        cp_wait0();
        __syncthreads();
        // convert STA fp32 -> sAhi/sAlo
        {
            const float* sp = staf + cvr * 68 + cvc;
            #pragma unroll
            for (int q = 0; q < 2; q++) {
                float4 u0 = *(const float4*)(sp + q * 8);
                float4 u1 = *(const float4*)(sp + q * 8 + 4);
                uint4 hi, lo;
                split2(u0.x, u0.y, hi.x, lo.x);
                split2(u0.z, u0.w, hi.y, lo.y);
                split2(u1.x, u1.y, hi.z, lo.z);
                split2(u1.z, u1.w, hi.w, lo.w);
                *(uint4*)(sAhi + cvr * 72 + cvc + q * 8) = hi;
                *(uint4*)(sAlo + cvr * 72 + cvc + q * 8) = lo;
            }
        }
        __syncthreads();
        if (c + 1 < NITER) {            // issue chunk c+1 (overlaps MMA below)
            const int k0 = (c + 1) * KC;
            const uint32_t bbuf = ((c + 1) & 1) * 18432u;
            #pragma unroll
            for (int j = 0; j < 4; j++) {
                int t = tid + 512 * j;
                int row = t >> 4, c4 = t & 15;
                cp16(su + OFF_STA + row * 272 + c4 * 16,
                     input + (size_t)(m0 + row) * DIN + k0 + c4 * 4);
            }
            #pragma unroll
            for (int j = 0; j < 2; j++) {
                int t = tid + 512 * j;
                int row = t >> 3, k8 = (t & 7) << 3;
                cp16(su + OFF_BHI + bbuf + row * 144 + k8 * 2, g_Wthi + row * DIN + k0 + k8);
                cp16(su + OFF_BLO + bbuf + row * 144 + k8 * 2, g_Wtlo + row * DIN + k0 + k8);
            }
            cp_commit();
        }
        // MMA chunk c (4 k-steps of 16)
        const __nv_bfloat16* Bhi = (__nv_bfloat16*)(sm + OFF_BHI + (c & 1) * 18432);
        const __nv_bfloat16* Blo = (__nv_bfloat16*)(sm + OFF_BLO + (c & 1) * 18432);
        #pragma unroll
        for (int ks = 0; ks < 4; ks++) {
            wmma::fragment<wmma::matrix_a, 16, 16, 16, __nv_bfloat16, wmma::row_major> fahi, falo;
            wmma::load_matrix_sync(fahi, sAhi + (w8 * 16) * 72 + ks * 16, 72);
            wmma::load_matrix_sync(falo, sAlo + (w8 * 16) * 72 + ks * 16, 72);
            #pragma unroll
            for (int nf = 0; nf < 4; nf++) {
                wmma::fragment<wmma::matrix_b, 16, 16, 16, __nv_bfloat16, wmma::col_major> fb;
                wmma::load_matrix_sync(fb, Bhi + (wg * 64 + nf * 16) * 72 + ks * 16, 72);
                wmma::mma_sync(fc[nf], fahi, fb, fc[nf]);
                wmma::mma_sync(fc[nf], falo, fb, fc[nf]);
                wmma::load_matrix_sync(fb, Blo + (wg * 64 + nf * 16) * 72 + ks * 16, 72);
                wmma::mma_sync(fc[nf], fahi, fb, fc[nf]);
            }
        }
    }
    __syncthreads();   // all MMA done before smem reuse

    // -------- epilogue --------
    float* xsf = (float*)(sm + OFF_XS);
    float* xs  = xsf + wid * (16 * XPITCH);
    float* W1s = (float*)(sm + OFF_W1S);

    #pragma unroll
    for (int nf = 0; nf < 4; nf++)
        wmma::store_matrix_sync(xs + nf * 16, fc[nf], XPITCH, wmma::mem_row_major);
    for (int i = tid; i < DH * DA; i += 512) W1s[i] = Watt1[i];
    __syncthreads();

    const float invn = rsqrtf(1.0f + 1e-5f);

    // phase A: BN + ReLU in-place + coalesced g_x store
    {
        int hr  = lane >> 4;
        int cc4 = (lane & 15) << 2;
        int c0  = wg * 64 + cc4;
        float4 b4 = __ldg((const float4*)(b1  + c0));
        float4 g4 = __ldg((const float4*)(g1  + c0));
        float4 e4 = __ldg((const float4*)(be1 + c0));
        float s0 = g4.x * invn, s1 = g4.y * invn, s2 = g4.z * invn, s3 = g4.w * invn;
        #pragma unroll
        for (int it = 0; it < 8; it++) {
            int r = it * 2 + hr;
            float4 a = *(float4*)(xs + r * XPITCH + cc4);
            float4 v;
            v.x = fmaxf((a.x + b4.x) * s0 + e4.x, 0.f);
            v.y = fmaxf((a.y + b4.y) * s1 + e4.y, 0.f);
            v.z = fmaxf((a.z + b4.z) * s2 + e4.z, 0.f);
            v.w = fmaxf((a.w + b4.w) * s3 + e4.w, 0.f);
            *(float4*)(xs + r * XPITCH + cc4) = v;
            *(float4*)(g_x + (size_t)(m0 + w8 * 16 + r) * DH + c0) = v;
        }
    }
    __syncthreads();   // all x in smem before cross-warp h reads

    // phase H: warp wid owns rows wid*8..wid*8+7; lane = h column (0..31)
    {
        const int hr0 = wid * 8;
        float* xrow = xsf + (wid >> 1) * (16 * XPITCH) + ((wid & 1) * 8) * XPITCH;
        float acc8[8];
        #pragma unroll
        for (int j = 0; j < 8; j++) acc8[j] = 0.f;
        for (int cc = 0; cc < DH; cc++) {
            float wv = W1s[cc * DA + lane];
            const float* xcol = xrow + (cc >> 6) * (8 * 16 * XPITCH) + (cc & 63);
            #pragma unroll
            for (int j = 0; j < 8; j++) acc8[j] += xcol[j * XPITCH] * wv;
        }
        float bt = __ldg(batt1 + lane);
        float gg = __ldg(g2 + lane) * invn;
        float bb = __ldg(be2 + lane);
        float w2 = __ldg(Watt2 + lane);
        float b2v = __ldg(batt2);
        #pragma unroll
        for (int j = 0; j < 8; j++) {
            float hv = tanhf((acc8[j] + bt) * gg + bb);
            float term = hv * w2;
            #pragma unroll
            for (int off = 16; off; off >>= 1)
                term += __shfl_xor_sync(0xffffffffu, term, off);
            if (lane == 0) g_s[m0 + hr0 + j] = term + b2v;
        }
    }
}

// ---------------- kernel 2: Z + exact top-64 (11-bit hist + survivor-list refine) ----------------
__global__ __launch_bounds__(1024) void select_topk()
{
    extern __shared__ char sm2[];
    unsigned* hist = (unsigned*)(sm2);
    unsigned* lkey = (unsigned*)(sm2 + 8192);
    int*      lidx = (int*)(sm2 + 8192 + LCAP * 4);
    int*      eqidx = (int*)(sm2 + 8192 + LCAP * 8);
    __shared__ float zp[32];
    __shared__ int sh_b, sh_cnt, sh_lc, sh_ovf, sh_cg, sh_ce;
    __shared__ unsigned selkey[KSEL];
    __shared__ int selidx[KSEL];

    const int tid = threadIdx.x;
    for (int i = tid; i < 2048; i += 1024) hist[i] = 0;
    if (tid == 0) { sh_lc = 0; sh_ovf = 0; }
    __syncthreads();

    float z = 0.f;
    for (int i = tid; i < NTOT; i += 1024) {
        float v = g_s[i];
        z += expf(v);
        atomicAdd(&hist[f2k(v) >> 21], 1u);
    }
    #pragma unroll
    for (int off = 16; off; off >>= 1) z += __shfl_xor_sync(0xffffffffu, z, off);
    if ((tid & 31) == 0) zp[tid >> 5] = z;
    __syncthreads();
    if (tid == 0) {
        float zz = 0.f;
        for (int i = 0; i < 32; i++) zz += zp[i];
        g_Z = zz;
        int cum = 0, b = 2047;
        for (; b > 0; b--) { if (cum + (int)hist[b] >= KSEL) break; cum += (int)hist[b]; }
        sh_b = b; sh_cnt = cum;
    }
    __syncthreads();
    int need = KSEL - sh_cnt;
    const unsigned b1 = (unsigned)sh_b;
    unsigned prefix = b1 << 21, mask = 0xFFE00000u;

    for (int i = tid; i < NTOT; i += 1024) {
        unsigned k = f2k(g_s[i]);
        if ((k >> 21) >= b1) {
            int p = atomicAdd(&sh_lc, 1);
            if (p < LCAP) { lkey[p] = k; lidx[p] = i; }
            else sh_ovf = 1;
        }
    }
    __syncthreads();
    const int lc = (sh_lc < LCAP) ? sh_lc : LCAP;
    const bool useList = (sh_ovf == 0);

    #pragma unroll
    for (int p3 = 0; p3 < 3; p3++) {
        const int shift = (p3 == 0) ? 13 : (p3 == 1) ? 5 : 0;
        const unsigned bm = (p3 == 2) ? 31u : 255u;
        __syncthreads();
        if (tid < 256) hist[tid] = 0;
        __syncthreads();
        if (useList) {
            for (int j = tid; j < lc; j += 1024) {
                unsigned k = lkey[j];
                if ((k & mask) == prefix) atomicAdd(&hist[(k >> shift) & bm], 1u);
            }
        } else {
            for (int i = tid; i < NTOT; i += 1024) {
                unsigned k = f2k(g_s[i]);
                if ((k & mask) == prefix) atomicAdd(&hist[(k >> shift) & bm], 1u);
            }
        }
        __syncthreads();
        if (tid == 0) {
            int cum = 0, b = (int)bm;
            for (; b > 0; b--) { if (cum + (int)hist[b] >= need) break; cum += (int)hist[b]; }
            sh_b = b; sh_cnt = cum;
        }
        __syncthreads();
        need -= sh_cnt;
        prefix |= ((unsigned)sh_b) << shift;
        mask |= bm << shift;
    }
    const unsigned T = prefix;
    const int e_need = need;

    if (tid == 0) { sh_cg = 0; sh_ce = 0; }
    __syncthreads();
    if (useList) {
        for (int j = tid; j < lc; j += 1024) {
            unsigned k = lkey[j];
            if (k > T) { int p = atomicAdd(&sh_cg, 1); selkey[p] = k; selidx[p] = lidx[j]; }
            else if (k == T) { int p = atomicAdd(&sh_ce, 1); if (p < EQCAP) eqidx[p] = lidx[j]; }
        }
    } else {
        for (int i = tid; i < NTOT; i += 1024) {
            unsigned k = f2k(g_s[i]);
            if (k > T) { int p = atomicAdd(&sh_cg, 1); selkey[p] = k; selidx[p] = i; }
            else if (k == T) { int p = atomicAdd(&sh_ce, 1); if (p < EQCAP) eqidx[p] = i; }
        }
    }
    __syncthreads();
    if (tid == 0) {
        int cg = sh_cg, ce = sh_ce;
        if (ce <= EQCAP) {
            for (int j = 0; j < e_need; j++) {
                int mn = j;
                for (int q = j + 1; q < ce; q++) if (eqidx[q] < eqidx[mn]) mn = q;
                int t = eqidx[j]; eqidx[j] = eqidx[mn]; eqidx[mn] = t;
            }
        } else {
            int cnt = 0;
            for (int i = 0; i < NTOT && cnt < e_need; i++)
                if (f2k(g_s[i]) == T) eqidx[cnt++] = i;
        }
        for (int j = 0; j < e_need; j++) { selkey[cg + j] = T; selidx[cg + j] = eqidx[j]; }
    }
    __syncthreads();
    if (tid < KSEL) {
        unsigned mk = selkey[tid]; int mi = selidx[tid];
        int rank = 0;
        for (int j = 0; j < KSEL; j++)
            rank += (selkey[j] > mk) || (selkey[j] == mk && selidx[j] < mi);
        g_topidx[rank] = mi;
    }
}

// ---------------- kernel 3a: zs, zq/zk/zv, attention -> zw (all in smem) ----------------
#define TA_ZS   0                        // 64*129 f = 33024
#define TA_WQ   33024                    // 128*36 f = 18432 (pitch 36 for float4)
#define TA_WK   51456
#define TA_WV   69888
#define TA_ZQ   88320                    // 64*33 f = 8448
#define TA_ZK   96768
#define TA_ZV   105216
#define TA_BYTES 113664
__global__ __launch_bounds__(1024) void tail_a(
    const float* __restrict__ Wq, const float* __restrict__ Wk, const float* __restrict__ Wv)
{
    extern __shared__ char sm3[];
    float* zs = (float*)(sm3 + TA_ZS);
    float* wq = (float*)(sm3 + TA_WQ);
    float* wk = (float*)(sm3 + TA_WK);
    float* wv = (float*)(sm3 + TA_WV);
    float* zq = (float*)(sm3 + TA_ZQ);
    float* zk = (float*)(sm3 + TA_ZK);
    float* zv = (float*)(sm3 + TA_ZV);
    __shared__ float aA[KSEL], w[KSEL];
    __shared__ int idx[KSEL];

    const int tid = threadIdx.x;
    const float Zs = g_Z;

    if (tid < KSEL) {
        int id = g_topidx[tid];
        idx[tid] = id;
        aA[tid] = expf(g_s[id]) / Zs;
    }
    for (int i = tid; i < DH * DA; i += 1024) {   // stage weights, pitch 36
        int r = i >> 5, c = i & 31;
        wq[r * 36 + c] = Wq[i];
        wk[r * 36 + c] = Wk[i];
        wv[r * 36 + c] = Wv[i];
    }
    __syncthreads();
    if (tid == 0) {                               // w = softmax(A_top64)
        float m = aA[0];
        for (int i = 1; i < KSEL; i++) m = fmaxf(m, aA[i]);
        float ssum = 0.f;
        for (int i = 0; i < KSEL; i++) { float e = expf(aA[i] - m); w[i] = e; ssum += e; }
        float rs = 1.0f / ssum;
        for (int i = 0; i < KSEL; i++) w[i] *= rs;
    }
    __syncthreads();
    for (int e = tid; e < KSEL * DH; e += 1024) { // zs = x[top] * w
        int i = e >> 7, j = e & 127;
        zs[i * 129 + j] = g_x[(size_t)idx[i] * DH + j] * w[i];
    }
    __syncthreads();
    if (tid < 384) {   // zq/zk/zv GEMM: 4 rows x 4 cols per thread, float4 weights
        int rg = tid / 24, slot = tid % 24;
        int mat = slot >> 3, c4 = (slot & 7) << 2;
        const float* W = (mat == 0) ? wq : (mat == 1) ? wk : wv;
        float* dst = (mat == 0) ? zq : (mat == 1) ? zk : zv;
        float a0[4], a1[4], a2[4], a3[4];
        #pragma unroll
        for (int c = 0; c < 4; c++) { a0[c] = a1[c] = a2[c] = a3[c] = 0.f; }
        const float* z0 = zs + (rg * 4) * 129;
        for (int kk = 0; kk < DH; kk++) {
            float4 wv4 = *(const float4*)(W + kk * 36 + c4);
            float x0 = z0[kk], x1 = z0[129 + kk], x2 = z0[258 + kk], x3 = z0[387 + kk];
            a0[0] += x0 * wv4.x; a0[1] += x0 * wv4.y; a0[2] += x0 * wv4.z; a0[3] += x0 * wv4.w;
            a1[0] += x1 * wv4.x; a1[1] += x1 * wv4.y; a1[2] += x1 * wv4.z; a1[3] += x1 * wv4.w;
            a2[0] += x2 * wv4.x; a2[1] += x2 * wv4.y; a2[2] += x2 * wv4.z; a2[3] += x2 * wv4.w;
            a3[0] += x3 * wv4.x; a3[1] += x3 * wv4.y; a3[2] += x3 * wv4.z; a3[3] += x3 * wv4.w;
        }
        #pragma unroll
        for (int c = 0; c < 4; c++) {
            dst[(rg * 4 + 0) * 33 + c4 + c] = a0[c];
            dst[(rg * 4 + 1) * 33 + c4 + c] = a1[c];
            dst[(rg * 4 + 2) * 33 + c4 + c] = a2[c];
            dst[(rg * 4 + 3) * 33 + c4 + c] = a3[c];
        }
    }
    __syncthreads();
    {   // row attention: one warp -> 2 rows
        int lane = tid & 31, wd = tid >> 5;
        #pragma unroll
        for (int rr = 0; rr < 2; rr++) {
            int i = wd * 2 + rr;
            float l0 = 0, l1 = 0;
            #pragma unroll
            for (int c = 0; c < DA; c++) {
                float qv = zq[i * 33 + c];
                l0 += qv * zk[lane * 33 + c];
                l1 += qv * zk[(lane + 32) * 33 + c];
            }
            float m = fmaxf(l0, l1);
            #pragma unroll
            for (int off = 16; off; off >>= 1)
                m = fmaxf(m, __shfl_xor_sync(0xffffffffu, m, off));
            float p0 = expf(l0 - m), p1 = expf(l1 - m);
            float ss = p0 + p1;
            #pragma unroll
            for (int off = 16; off; off >>= 1) ss += __shfl_xor_sync(0xffffffffu, ss, off);
            float rs = 1.0f / ss;
            p0 *= rs; p1 *= rs;
            float acc = 0.f;
            #pragma unroll
            for (int j = 0; j < 32; j++) {
                float pj = __shfl_sync(0xffffffffu, p0, j);
                acc += pj * zv[j * 33 + lane];
            }
            #pragma unroll
            for (int j = 0; j < 32; j++) {
                float pj = __shfl_sync(0xffffffffu, p1, j);
                acc += pj * zv[(j + 32) * 33 + lane];
            }
            g_zw[i * DA + lane] = acc;
        }
    }
}

// ---------------- kernel 3b: Wz partials (16 blocks) ----------------
__global__ __launch_bounds__(128) void tail_b(const float* __restrict__ Wz)
{
    __shared__ float zws[128];
    const int g = blockIdx.x, n = threadIdx.x;
    const int mb = g * 128;
    zws[n] = g_zw[mb + n];
    __syncthreads();
    float acc = 0.f;
    #pragma unroll 8
    for (int m = 0; m < 128; m++)
        acc += zws[m] * __ldg(Wz + (size_t)(mb + m) * DH + n);
    g_part[g * DH + n] = acc;
}

// ---------------- kernel 3c: reduce + relu + fc ----------------
__global__ __launch_bounds__(128) void tail_c(
    const float* __restrict__ bz, const float* __restrict__ Wf,
    const float* __restrict__ bf, float* __restrict__ out)
{
    __shared__ float red[4];
    const int t = threadIdx.x;
    float a = bz[t];
    #pragma unroll
    for (int g = 0; g < 16; g++) a += g_part[g * DH + t];
    float zv = fmaxf(a, 0.f) * Wf[t];
    #pragma unroll
    for (int off = 16; off; off >>= 1) zv += __shfl_xor_sync(0xffffffffu, zv, off);
    if ((t & 31) == 0) red[t >> 5] = zv;
    __syncthreads();
    if (t == 0) out[0] = red[0] + red[1] + red[2] + red[3] + bf[0];
}

// ---------------- host launcher ----------------
extern "C" void kernel_launch(void* const* d_in, const int* in_sizes, int n_in,
                              void* d_out, int out_size)
{
    const float* input = (const float*)d_in[0];
    const float* W1    = (const float*)d_in[1];
    const float* b1    = (const float*)d_in[2];
    const float* g1    = (const float*)d_in[3];
    const float* be1   = (const float*)d_in[4];
    const float* Watt1 = (const float*)d_in[5];
    const float* batt1 = (const float*)d_in[6];
    const float* g2    = (const float*)d_in[7];
    const float* be2   = (const float*)d_in[8];
    const float* Watt2 = (const float*)d_in[9];
    const float* batt2 = (const float*)d_in[10];
    const float* Wq    = (const float*)d_in[11];
    const float* Wk    = (const float*)d_in[12];
    const float* Wv    = (const float*)d_in[13];
    const float* Wz    = (const float*)d_in[14];
    const float* bz    = (const float*)d_in[15];
    const float* Wf    = (const float*)d_in[16];
    const float* bf    = (const float*)d_in[17];

    static const int SEL_BYTES = 8192 + LCAP * 8 + EQCAP * 4;
    cudaFuncSetAttribute(fused_main_tc, cudaFuncAttributeMaxDynamicSharedMemorySize, SM_BYTES);
    cudaFuncSetAttribute(select_topk,  cudaFuncAttributeMaxDynamicSharedMemorySize, SEL_BYTES);
    cudaFuncSetAttribute(tail_a,       cudaFuncAttributeMaxDynamicSharedMemorySize, TA_BYTES);

    conv_w1<<<DH, 256>>>(W1, Wz);
    fused_main_tc<<<NTOT / 128, 512, SM_BYTES>>>(input, b1, g1, be1,
                                                 Watt1, batt1, g2, be2, Watt2, batt2);
    select_topk<<<1, 1024, SEL_BYTES>>>();
    tail_a<<<1, 1024, TA_BYTES>>>(Wq, Wk, Wv);
    tail_b<<<16, 128>>>(Wz);
    tail_c<<<1, 128>>>(bz, Wf, bf, (float*)d_out);
}

// round 9
// speedup vs baseline: 1.0674x; 1.0674x over previous
#include <cuda_runtime.h>
#include <cuda_bf16.h>
#include <mma.h>
#include <math.h>
#include <stdint.h>

using namespace nvcuda;

#define NTOT 131072
#define DIN 768
#define DH 128
#define DA 32
#define KSEL 64
#define KC 32
#define NITER 24
#define LCAP 4096
#define EQCAP 4096
#define NBLK (NTOT / 128)

// ---------------- device scratch (allocation-free) ----------------
__device__ float          g_x[(size_t)NTOT * DH];     // post-activation x rows (64 MB)
__device__ float          g_s[NTOT];                  // attention scores
__device__ float          g_Z;                        // softmax denominator
__device__ int            g_topidx[KSEL];             // top-64 indices, value-desc order
__device__ float          g_zw[KSEL * DA];
__device__ float          g_part[16 * DH];
__device__ float          g_dummy[DH];                // L2-prefetch sink
__device__ unsigned       g_hist[2048];               // 11-bit score histogram
__device__ float          g_zpart[NBLK];              // per-block sum exp(s)
__device__ __nv_bfloat16  g_Wthi[DH * DIN];           // W1^T hi  [n][k]
__device__ __nv_bfloat16  g_Wtlo[DH * DIN];           // W1^T lo  [n][k]

// ---------------- fused kernel smem map (bytes) ----------------
// mainloop: STA 128x36f (144B pitch) = 18432; AHI/ALO 128x40 bf16 = 10240 each;
//           BHI[2] / BLO[2] 10240 per buffer
#define OFF_STA 0
#define OFF_AHI 18432
#define OFF_ALO 28672
#define OFF_BHI 38912
#define OFF_BLO 59392
// epilogue reuse: XS = 16 warps x (16 x 76 f) = 77824 ; W1S 128x32 f = 16384
#define XPITCH 76
#define OFF_XS  0
#define OFF_W1S 77824
#define SM_BYTES 94208

__device__ __forceinline__ uint32_t smem_u32(const void* p) {
    uint32_t a;
    asm("{ .reg .u64 t; cvta.to.shared.u64 t, %1; cvt.u32.u64 %0, t; }" : "=r"(a) : "l"(p));
    return a;
}
__device__ __forceinline__ void cp16(uint32_t s, const void* g) {
    asm volatile("cp.async.cg.shared.global [%0], [%1], 16;" :: "r"(s), "l"(g));
}
__device__ __forceinline__ void cp_commit() { asm volatile("cp.async.commit_group;" ::: "memory"); }
__device__ __forceinline__ void cp_wait0()  { asm volatile("cp.async.wait_group 0;" ::: "memory"); }

// float -> monotone sortable uint
__device__ __forceinline__ unsigned f2k(float f) {
    unsigned u = __float_as_uint(f);
    return u ^ ((u & 0x80000000u) ? 0xFFFFFFFFu : 0x80000000u);
}
// pack two floats' bf16 hi parts and bf16 residual lo parts
__device__ __forceinline__ void split2(float x, float y, uint32_t& hi2, uint32_t& lo2) {
    __nv_bfloat16 hx = __float2bfloat16(x), hy = __float2bfloat16(y);
    float rx = x - __bfloat162float(hx), ry = y - __bfloat162float(hy);
    __nv_bfloat16 lx = __float2bfloat16(rx), ly = __float2bfloat16(ry);
    hi2 = (uint32_t)__bfloat16_as_ushort(hx) | ((uint32_t)__bfloat16_as_ushort(hy) << 16);
    lo2 = (uint32_t)__bfloat16_as_ushort(lx) | ((uint32_t)__bfloat16_as_ushort(ly) << 16);
}

// ---------------- kernel 0: W1 -> bf16 hi/lo transpose, zero hist, L2-warm Wz ----------------
__global__ __launch_bounds__(256) void conv_w1(const float* __restrict__ W1,
                                               const float* __restrict__ Wz) {
    int n = blockIdx.x;
    if (threadIdx.x < 16) g_hist[n * 16 + threadIdx.x] = 0u;   // zero 2048 bins across 128 blocks
    for (int k = threadIdx.x; k < DIN; k += 256) {
        float v = W1[(size_t)k * DH + n];
        __nv_bfloat16 h = __float2bfloat16(v);
        g_Wthi[n * DIN + k] = h;
        g_Wtlo[n * DIN + k] = __float2bfloat16(v - __bfloat162float(h));
    }
    // touch Wz slice: 2048 rows / 128 blocks = 16 rows per block
    float acc = 0.f;
    const float* wzb = Wz + (size_t)n * 16 * DH;
    for (int i = threadIdx.x; i < 16 * DH; i += 256) acc += wzb[i];
    __shared__ float red[8];
    #pragma unroll
    for (int off = 16; off; off >>= 1) acc += __shfl_xor_sync(0xffffffffu, acc, off);
    if ((threadIdx.x & 31) == 0) red[threadIdx.x >> 5] = acc;
    __syncthreads();
    if (threadIdx.x == 0) {
        float t = 0.f;
        for (int i = 0; i < 8; i++) t += red[i];
        g_dummy[n] = t;
    }
}

// ---------------- kernel 1: WMMA bf16-split GEMM + BN/ReLU + h + s + hist/Z ----------------
__global__ __launch_bounds__(512, 2) void fused_main_tc(
    const float* __restrict__ input,
    const float* __restrict__ b1, const float* __restrict__ g1, const float* __restrict__ be1,
    const float* __restrict__ Watt1, const float* __restrict__ batt1,
    const float* __restrict__ g2, const float* __restrict__ be2,
    const float* __restrict__ Watt2, const float* __restrict__ batt2)
{
    extern __shared__ char sm[];
    __shared__ float sarr[128];
    __shared__ float zred[4];
    const uint32_t su = smem_u32(sm);
    float*         staf = (float*)(sm + OFF_STA);
    __nv_bfloat16* sAhi = (__nv_bfloat16*)(sm + OFF_AHI);
    __nv_bfloat16* sAlo = (__nv_bfloat16*)(sm + OFF_ALO);

    const int tid = threadIdx.x;
    const int lane = tid & 31, wid = tid >> 5;
    const int wg = wid >> 3;          // 0/1: N half
    const int w8 = wid & 7;           // 0..7: M group of 16 rows
    const int m0 = blockIdx.x * 128;

    // loader indices (KC=32)
    const int ar0 = tid >> 3,         akk0 = (tid & 7) << 2;          // A rows 0..63
    const int ar1 = (tid + 512) >> 3, akk1 = ((tid + 512) & 7) << 2;  // A rows 64..127
    const int br = tid >> 2,          bkk = (tid & 3) << 3;           // B rows 0..127

    wmma::fragment<wmma::accumulator, 16, 16, 16, float> fc[4];
    #pragma unroll
    for (int j = 0; j < 4; j++) wmma::fill_fragment(fc[j], 0.0f);

    // prologue: issue chunk 0
    {
        cp16(su + OFF_STA + ar0 * 144 + akk0 * 4, input + (size_t)(m0 + ar0) * DIN + akk0);
        cp16(su + OFF_STA + ar1 * 144 + akk1 * 4, input + (size_t)(m0 + ar1) * DIN + akk1);
        cp16(su + OFF_BHI + br * 80 + bkk * 2, g_Wthi + br * DIN + bkk);
        cp16(su + OFF_BLO + br * 80 + bkk * 2, g_Wtlo + br * DIN + bkk);
        cp_commit();
    }

    const int cvr = tid >> 2, cvc = (tid & 3) << 3;   // convert: 4 thr/row, 8 floats each

    for (int c = 0; c < NITER; c++) {
        cp_wait0();
        __syncthreads();
        // convert STA fp32 -> sAhi/sAlo
        {
            float4 u0 = *(const float4*)(staf + cvr * 36 + cvc);
            float4 u1 = *(const float4*)(staf + cvr * 36 + cvc + 4);
            uint4 hi, lo;
            split2(u0.x, u0.y, hi.x, lo.x);
            split2(u0.z, u0.w, hi.y, lo.y);
            split2(u1.x, u1.y, hi.z, lo.z);
            split2(u1.z, u1.w, hi.w, lo.w);
            *(uint4*)(sAhi + cvr * 40 + cvc) = hi;
            *(uint4*)(sAlo + cvr * 40 + cvc) = lo;
        }
        __syncthreads();
        if (c + 1 < NITER) {             // issue chunk c+1 (overlaps MMA below)
            const int k0 = (c + 1) * KC;
            const uint32_t bbuf = ((c + 1) & 1) * 10240u;
            cp16(su + OFF_STA + ar0 * 144 + akk0 * 4, input + (size_t)(m0 + ar0) * DIN + k0 + akk0);
            cp16(su + OFF_STA + ar1 * 144 + akk1 * 4, input + (size_t)(m0 + ar1) * DIN + k0 + akk1);
            cp16(su + OFF_BHI + bbuf + br * 80 + bkk * 2, g_Wthi + br * DIN + k0 + bkk);
            cp16(su + OFF_BLO + bbuf + br * 80 + bkk * 2, g_Wtlo + br * DIN + k0 + bkk);
            cp_commit();
        }
        // MMA chunk c (2 k-steps of 16)
        const __nv_bfloat16* Bhi = (__nv_bfloat16*)(sm + OFF_BHI + (c & 1) * 10240);
        const __nv_bfloat16* Blo = (__nv_bfloat16*)(sm + OFF_BLO + (c & 1) * 10240);
        #pragma unroll
        for (int ks = 0; ks < 2; ks++) {
            wmma::fragment<wmma::matrix_a, 16, 16, 16, __nv_bfloat16, wmma::row_major> fahi, falo;
            wmma::load_matrix_sync(fahi, sAhi + (w8 * 16) * 40 + ks * 16, 40);
            wmma::load_matrix_sync(falo, sAlo + (w8 * 16) * 40 + ks * 16, 40);
            #pragma unroll
            for (int nf = 0; nf < 4; nf++) {
                wmma::fragment<wmma::matrix_b, 16, 16, 16, __nv_bfloat16, wmma::col_major> fb;
                wmma::load_matrix_sync(fb, Bhi + (wg * 64 + nf * 16) * 40 + ks * 16, 40);
                wmma::mma_sync(fc[nf], fahi, fb, fc[nf]);
                wmma::mma_sync(fc[nf], falo, fb, fc[nf]);
                wmma::load_matrix_sync(fb, Blo + (wg * 64 + nf * 16) * 40 + ks * 16, 40);
                wmma::mma_sync(fc[nf], fahi, fb, fc[nf]);
            }
        }
    }
    __syncthreads();   // all MMA done before smem reuse

    // -------- epilogue --------
    float* xsf = (float*)(sm + OFF_XS);
    float* xs  = xsf + wid * (16 * XPITCH);
    float* W1s = (float*)(sm + OFF_W1S);

    #pragma unroll
    for (int nf = 0; nf < 4; nf++)
        wmma::store_matrix_sync(xs + nf * 16, fc[nf], XPITCH, wmma::mem_row_major);
    for (int i = tid; i < DH * DA; i += 512) W1s[i] = Watt1[i];
    __syncthreads();

    const float invn = rsqrtf(1.0f + 1e-5f);

    // phase A: BN + ReLU in-place + coalesced g_x store
    {
        int hr  = lane >> 4;
        int cc4 = (lane & 15) << 2;
        int c0  = wg * 64 + cc4;
        float4 b4 = __ldg((const float4*)(b1  + c0));
        float4 g4 = __ldg((const float4*)(g1  + c0));
        float4 e4 = __ldg((const float4*)(be1 + c0));
        float s0 = g4.x * invn, s1 = g4.y * invn, s2 = g4.z * invn, s3 = g4.w * invn;
        #pragma unroll
        for (int it = 0; it < 8; it++) {
            int r = it * 2 + hr;
            float4 a = *(float4*)(xs + r * XPITCH + cc4);
            float4 v;
            v.x = fmaxf((a.x + b4.x) * s0 + e4.x, 0.f);
            v.y = fmaxf((a.y + b4.y) * s1 + e4.y, 0.f);
            v.z = fmaxf((a.z + b4.z) * s2 + e4.z, 0.f);
            v.w = fmaxf((a.w + b4.w) * s3 + e4.w, 0.f);
            *(float4*)(xs + r * XPITCH + cc4) = v;
            *(float4*)(g_x + (size_t)(m0 + w8 * 16 + r) * DH + c0) = v;
        }
    }
    __syncthreads();   // all x in smem before cross-warp h reads

    // phase H: warp wid owns rows wid*8..wid*8+7; lane = h column (0..31)
    {
        const int hr0 = wid * 8;
        float* xrow = xsf + (wid >> 1) * (16 * XPITCH) + ((wid & 1) * 8) * XPITCH;
        float acc8[8];
        #pragma unroll
        for (int j = 0; j < 8; j++) acc8[j] = 0.f;
        for (int cc = 0; cc < DH; cc++) {
            float wv = W1s[cc * DA + lane];
            const float* xcol = xrow + (cc >> 6) * (8 * 16 * XPITCH) + (cc & 63);
            #pragma unroll
            for (int j = 0; j < 8; j++) acc8[j] += xcol[j * XPITCH] * wv;
        }
        float bt = __ldg(batt1 + lane);
        float gg = __ldg(g2 + lane) * invn;
        float bb = __ldg(be2 + lane);
        float w2 = __ldg(Watt2 + lane);
        float b2v = __ldg(batt2);
        #pragma unroll
        for (int j = 0; j < 8; j++) {
            float hv = tanhf((acc8[j] + bt) * gg + bb);
            float term = hv * w2;
            #pragma unroll
            for (int off = 16; off; off >>= 1)
                term += __shfl_xor_sync(0xffffffffu, term, off);
            if (lane == 0) {
                float sv = term + b2v;
                g_s[m0 + hr0 + j] = sv;
                sarr[hr0 + j] = sv;
            }
        }
    }
    __syncthreads();

    // phase S: histogram + deterministic block Z-partial
    if (tid < 128) {
        float sv = sarr[tid];
        atomicAdd(&g_hist[f2k(sv) >> 21], 1u);
        float e = expf(sv);
        #pragma unroll
        for (int off = 16; off; off >>= 1) e += __shfl_xor_sync(0xffffffffu, e, off);
        if ((tid & 31) == 0) zred[tid >> 5] = e;
    }
    __syncthreads();
    if (tid == 0)
        g_zpart[blockIdx.x] = ((zred[0] + zred[1]) + (zred[2] + zred[3]));
}

// ---------------- kernel 2: Z reduce + exact top-64 (prebuilt hist + survivor refine) ----------------
__global__ __launch_bounds__(1024) void select_topk()
{
    extern __shared__ char sm2[];
    unsigned* hist = (unsigned*)(sm2);                 // 256 refine bins (+ padding)
    unsigned* lkey = (unsigned*)(sm2 + 8192);
    int*      lidx = (int*)(sm2 + 8192 + LCAP * 4);
    int*      eqidx = (int*)(sm2 + 8192 + LCAP * 8);
    __shared__ float zp[32];
    __shared__ int sh_b, sh_cnt, sh_lc, sh_ovf, sh_cg, sh_ce;
    __shared__ unsigned selkey[KSEL];
    __shared__ int selidx[KSEL];

    const int tid = threadIdx.x;
    if (tid == 0) { sh_lc = 0; sh_ovf = 0; }

    // Z: deterministic fixed-order tree over NBLK partials
    {
        float z = (tid < NBLK) ? g_zpart[tid] : 0.f;
        #pragma unroll
        for (int off = 16; off; off >>= 1) z += __shfl_xor_sync(0xffffffffu, z, off);
        if ((tid & 31) == 0) zp[tid >> 5] = z;
    }
    __syncthreads();
    if (tid == 0) {
        float zz = 0.f;
        for (int i = 0; i < 32; i++) zz += zp[i];
        g_Z = zz;
        int cum = 0, b = 2047;
        for (; b > 0; b--) { if (cum + (int)g_hist[b] >= KSEL) break; cum += (int)g_hist[b]; }
        sh_b = b; sh_cnt = cum;
    }
    __syncthreads();
    int need = KSEL - sh_cnt;
    const unsigned b1 = (unsigned)sh_b;
    unsigned prefix = b1 << 21, mask = 0xFFE00000u;

    // survivor scan (single full pass over g_s)
    for (int i = tid; i < NTOT; i += 1024) {
        unsigned k = f2k(g_s[i]);
        if ((k >> 21) >= b1) {
            int p = atomicAdd(&sh_lc, 1);
            if (p < LCAP) { lkey[p] = k; lidx[p] = i; }
            else sh_ovf = 1;
        }
    }
    __syncthreads();
    const int lc = (sh_lc < LCAP) ? sh_lc : LCAP;
    const bool useList = (sh_ovf == 0);

    // refine remaining 21 bits: (shift,width) = (13,8),(5,8),(0,5)
    #pragma unroll
    for (int p3 = 0; p3 < 3; p3++) {
        const int shift = (p3 == 0) ? 13 : (p3 == 1) ? 5 : 0;
        const unsigned bm = (p3 == 2) ? 31u : 255u;
        __syncthreads();
        if (tid < 256) hist[tid] = 0;
        __syncthreads();
        if (useList) {
            for (int j = tid; j < lc; j += 1024) {
                unsigned k = lkey[j];
                if ((k & mask) == prefix) atomicAdd(&hist[(k >> shift) & bm], 1u);
            }
        } else {
            for (int i = tid; i < NTOT; i += 1024) {
                unsigned k = f2k(g_s[i]);
                if ((k & mask) == prefix) atomicAdd(&hist[(k >> shift) & bm], 1u);
            }
        }
        __syncthreads();
        if (tid == 0) {
            int cum = 0, b = (int)bm;
            for (; b > 0; b--) { if (cum + (int)hist[b] >= need) break; cum += (int)hist[b]; }
            sh_b = b; sh_cnt = cum;
        }
        __syncthreads();
        need -= sh_cnt;
        prefix |= ((unsigned)sh_b) << shift;
        mask |= bm << shift;
    }
    const unsigned T = prefix;
    const int e_need = need;

    if (tid == 0) { sh_cg = 0; sh_ce = 0; }
    __syncthreads();
    if (useList) {
        for (int j = tid; j < lc; j += 1024) {
            unsigned k = lkey[j];
            if (k > T) { int p = atomicAdd(&sh_cg, 1); selkey[p] = k; selidx[p] = lidx[j]; }
            else if (k == T) { int p = atomicAdd(&sh_ce, 1); if (p < EQCAP) eqidx[p] = lidx[j]; }
        }
    } else {
        for (int i = tid; i < NTOT; i += 1024) {
            unsigned k = f2k(g_s[i]);
            if (k > T) { int p = atomicAdd(&sh_cg, 1); selkey[p] = k; selidx[p] = i; }
            else if (k == T) { int p = atomicAdd(&sh_ce, 1); if (p < EQCAP) eqidx[p] = i; }
        }
    }
    __syncthreads();
    if (tid == 0) {
        int cg = sh_cg, ce = sh_ce;
        if (ce <= EQCAP) {
            for (int j = 0; j < e_need; j++) {           // e smallest indices among ties
                int mn = j;
                for (int q = j + 1; q < ce; q++) if (eqidx[q] < eqidx[mn]) mn = q;
                int t = eqidx[j]; eqidx[j] = eqidx[mn]; eqidx[mn] = t;
            }
        } else {                                         // pathological tie fallback
            int cnt = 0;
            for (int i = 0; i < NTOT && cnt < e_need; i++)
                if (f2k(g_s[i]) == T) eqidx[cnt++] = i;
        }
        for (int j = 0; j < e_need; j++) { selkey[cg + j] = T; selidx[cg + j] = eqidx[j]; }
    }
    __syncthreads();
    if (tid < KSEL) {   // rank: key desc, index asc (stable argsort(-A))
        unsigned mk = selkey[tid]; int mi = selidx[tid];
        int rank = 0;
        for (int j = 0; j < KSEL; j++)
            rank += (selkey[j] > mk) || (selkey[j] == mk && selidx[j] < mi);
        g_topidx[rank] = mi;
    }
}

// ---------------- kernel 3a: zs, zq/zk/zv, attention -> zw (all in smem) ----------------
#define TA_ZS   0                        // 64*129 f = 33024
#define TA_WQ   33024                    // 128*36 f = 18432 (pitch 36 for float4)
#define TA_WK   51456
#define TA_WV   69888
#define TA_ZQ   88320                    // 64*33 f = 8448
#define TA_ZK   96768
#define TA_ZV   105216
#define TA_BYTES 113664
__global__ __launch_bounds__(1024) void tail_a(
    const float* __restrict__ Wq, const float* __restrict__ Wk, const float* __restrict__ Wv)
{
    extern __shared__ char sm3[];
    float* zs = (float*)(sm3 + TA_ZS);
    float* wq = (float*)(sm3 + TA_WQ);
    float* wk = (float*)(sm3 + TA_WK);
    float* wv = (float*)(sm3 + TA_WV);
    float* zq = (float*)(sm3 + TA_ZQ);
    float* zk = (float*)(sm3 + TA_ZK);
    float* zv = (float*)(sm3 + TA_ZV);
    __shared__ float aA[KSEL], w[KSEL];
    __shared__ int idx[KSEL];

    const int tid = threadIdx.x;
    const float Zs = g_Z;

    if (tid < KSEL) {
        int id = g_topidx[tid];
        idx[tid] = id;
        aA[tid] = expf(g_s[id]) / Zs;
    }
    for (int i = tid; i < DH * DA; i += 1024) {   // stage weights, pitch 36
        int r = i >> 5, c = i & 31;
        wq[r * 36 + c] = Wq[i];
        wk[r * 36 + c] = Wk[i];
        wv[r * 36 + c] = Wv[i];
    }
    __syncthreads();
    if (tid == 0) {                               // w = softmax(A_top64)
        float m = aA[0];
        for (int i = 1; i < KSEL; i++) m = fmaxf(m, aA[i]);
        float ssum = 0.f;
        for (int i = 0; i < KSEL; i++) { float e = expf(aA[i] - m); w[i] = e; ssum += e; }
        float rs = 1.0f / ssum;
        for (int i = 0; i < KSEL; i++) w[i] *= rs;
    }
    __syncthreads();
    for (int e = tid; e < KSEL * DH; e += 1024) { // zs = x[top] * w
        int i = e >> 7, j = e & 127;
        zs[i * 129 + j] = g_x[(size_t)idx[i] * DH + j] * w[i];
    }
    __syncthreads();
    if (tid < 384) {   // zq/zk/zv GEMM: 4 rows x 4 cols per thread, float4 weights
        int rg = tid / 24, slot = tid % 24;
        int mat = slot >> 3, c4 = (slot & 7) << 2;
        const float* W = (mat == 0) ? wq : (mat == 1) ? wk : wv;
        float* dst = (mat == 0) ? zq : (mat == 1) ? zk : zv;
        float a0[4], a1[4], a2[4], a3[4];
        #pragma unroll
        for (int c = 0; c < 4; c++) { a0[c] = a1[c] = a2[c] = a3[c] = 0.f; }
        const float* z0 = zs + (rg * 4) * 129;
        for (int kk = 0; kk < DH; kk++) {
            float4 wv4 = *(const float4*)(W + kk * 36 + c4);
            float x0 = z0[kk], x1 = z0[129 + kk], x2 = z0[258 + kk], x3 = z0[387 + kk];
            a0[0] += x0 * wv4.x; a0[1] += x0 * wv4.y; a0[2] += x0 * wv4.z; a0[3] += x0 * wv4.w;
            a1[0] += x1 * wv4.x; a1[1] += x1 * wv4.y; a1[2] += x1 * wv4.z; a1[3] += x1 * wv4.w;
            a2[0] += x2 * wv4.x; a2[1] += x2 * wv4.y; a2[2] += x2 * wv4.z; a2[3] += x2 * wv4.w;
            a3[0] += x3 * wv4.x; a3[1] += x3 * wv4.y; a3[2] += x3 * wv4.z; a3[3] += x3 * wv4.w;
        }
        #pragma unroll
        for (int c = 0; c < 4; c++) {
            dst[(rg * 4 + 0) * 33 + c4 + c] = a0[c];
            dst[(rg * 4 + 1) * 33 + c4 + c] = a1[c];
            dst[(rg * 4 + 2) * 33 + c4 + c] = a2[c];
            dst[(rg * 4 + 3) * 33 + c4 + c] = a3[c];
        }
    }
    __syncthreads();
    {   // row attention: one warp -> 2 rows
        int lane = tid & 31, wd = tid >> 5;
        #pragma unroll
        for (int rr = 0; rr < 2; rr++) {
            int i = wd * 2 + rr;
            float l0 = 0, l1 = 0;
            #pragma unroll
            for (int c = 0; c < DA; c++) {
                float qv = zq[i * 33 + c];
                l0 += qv * zk[lane * 33 + c];
                l1 += qv * zk[(lane + 32) * 33 + c];
            }
            float m = fmaxf(l0, l1);
            #pragma unroll
            for (int off = 16; off; off >>= 1)
                m = fmaxf(m, __shfl_xor_sync(0xffffffffu, m, off));
            float p0 = expf(l0 - m), p1 = expf(l1 - m);
            float ss = p0 + p1;
            #pragma unroll
            for (int off = 16; off; off >>= 1) ss += __shfl_xor_sync(0xffffffffu, ss, off);
            float rs = 1.0f / ss;
            p0 *= rs; p1 *= rs;
            float acc = 0.f;
            #pragma unroll
            for (int j = 0; j < 32; j++) {
                float pj = __shfl_sync(0xffffffffu, p0, j);
                acc += pj * zv[j * 33 + lane];
            }
            #pragma unroll
            for (int j = 0; j < 32; j++) {
                float pj = __shfl_sync(0xffffffffu, p1, j);
                acc += pj * zv[(j + 32) * 33 + lane];
            }
            g_zw[i * DA + lane] = acc;
        }
    }
}

// ---------------- kernel 3b: Wz partials (16 blocks) ----------------
__global__ __launch_bounds__(128) void tail_b(const float* __restrict__ Wz)
{
    __shared__ float zws[128];
    const int g = blockIdx.x, n = threadIdx.x;
    const int mb = g * 128;
    zws[n] = g_zw[mb + n];
    __syncthreads();
    float acc = 0.f;
    #pragma unroll 8
    for (int m = 0; m < 128; m++)
        acc += zws[m] * __ldg(Wz + (size_t)(mb + m) * DH + n);
    g_part[g * DH + n] = acc;
}

// ---------------- kernel 3c: reduce + relu + fc ----------------
__global__ __launch_bounds__(128) void tail_c(
    const float* __restrict__ bz, const float* __restrict__ Wf,
    const float* __restrict__ bf, float* __restrict__ out)
{
    __shared__ float red[4];
    const int t = threadIdx.x;
    float a = bz[t];
    #pragma unroll
    for (int g = 0; g < 16; g++) a += g_part[g * DH + t];
    float zv = fmaxf(a, 0.f) * Wf[t];
    #pragma unroll
    for (int off = 16; off; off >>= 1) zv += __shfl_xor_sync(0xffffffffu, zv, off);
    if ((t & 31) == 0) red[t >> 5] = zv;
    __syncthreads();
    if (t == 0) out[0] = red[0] + red[1] + red[2] + red[3] + bf[0];
}

// ---------------- host launcher ----------------
extern "C" void kernel_launch(void* const* d_in, const int* in_sizes, int n_in,
                              void* d_out, int out_size)
{
    const float* input = (const float*)d_in[0];
    const float* W1    = (const float*)d_in[1];
    const float* b1    = (const float*)d_in[2];
    const float* g1    = (const float*)d_in[3];
    const float* be1   = (const float*)d_in[4];
    const float* Watt1 = (const float*)d_in[5];
    const float* batt1 = (const float*)d_in[6];
    const float* g2    = (const float*)d_in[7];
    const float* be2   = (const float*)d_in[8];
    const float* Watt2 = (const float*)d_in[9];
    const float* batt2 = (const float*)d_in[10];
    const float* Wq    = (const float*)d_in[11];
    const float* Wk    = (const float*)d_in[12];
    const float* Wv    = (const float*)d_in[13];
    const float* Wz    = (const float*)d_in[14];
    const float* bz    = (const float*)d_in[15];
    const float* Wf    = (const float*)d_in[16];
    const float* bf    = (const float*)d_in[17];

    static const int SEL_BYTES = 8192 + LCAP * 8 + EQCAP * 4;
    cudaFuncSetAttribute(fused_main_tc, cudaFuncAttributeMaxDynamicSharedMemorySize, SM_BYTES);
    cudaFuncSetAttribute(select_topk,  cudaFuncAttributeMaxDynamicSharedMemorySize, SEL_BYTES);
    cudaFuncSetAttribute(tail_a,       cudaFuncAttributeMaxDynamicSharedMemorySize, TA_BYTES);

    conv_w1<<<DH, 256>>>(W1, Wz);
    fused_main_tc<<<NBLK, 512, SM_BYTES>>>(input, b1, g1, be1,
                                           Watt1, batt1, g2, be2, Watt2, batt2);
    select_topk<<<1, 1024, SEL_BYTES>>>();
    tail_a<<<1, 1024, TA_BYTES>>>(Wq, Wk, Wv);
    tail_b<<<16, 128>>>(Wz);
    tail_c<<<1, 128>>>(bz, Wf, bf, (float*)d_out);
}

// round 10
// speedup vs baseline: 1.1472x; 1.0747x over previous
#include <cuda_runtime.h>
#include <cuda_bf16.h>
#include <mma.h>
#include <math.h>
#include <stdint.h>

using namespace nvcuda;

#define NTOT 131072
#define DIN 768
#define DH 128
#define DA 32
#define KSEL 64
#define KC 32
#define NITER 24
#define LCAP 4096
#define EQCAP 4096
#define NBLK (NTOT / 128)

// ---------------- device scratch (allocation-free) ----------------
__device__ float          g_x[(size_t)NTOT * DH];     // post-activation x rows (64 MB)
__device__ float          g_s[NTOT];                  // attention scores
__device__ float          g_Z;                        // softmax denominator
__device__ int            g_topidx[KSEL];             // top-64 indices, value-desc order
__device__ float          g_zw[KSEL * DA];
__device__ float          g_part[16 * DH];
__device__ float          g_dummy[DH];                // L2-prefetch sink
__device__ unsigned       g_hist[2048];               // 11-bit score histogram
__device__ float          g_zpart[NBLK];              // per-block sum exp(s)
__device__ __nv_bfloat16  g_Wthi[DH * DIN];           // W1^T hi  [n][k]
__device__ __nv_bfloat16  g_Wtlo[DH * DIN];           // W1^T lo  [n][k]

// ---------------- fused kernel smem map (bytes) ----------------
// mainloop: STA 128x36f (144B pitch) = 18432; AHI/ALO 128x40 bf16 = 10240 each;
//           BHI[2] / BLO[2] 10240 per buffer
#define OFF_STA 0
#define OFF_AHI 18432
#define OFF_ALO 28672
#define OFF_BHI 38912
#define OFF_BLO 59392
// epilogue reuse: XS = 8 warps x (32 x 76 f) = 77824 ; W1S 128x32 f = 16384
#define XPITCH 76
#define OFF_XS  0
#define OFF_W1S 77824
#define SM_BYTES 94208

__device__ __forceinline__ uint32_t smem_u32(const void* p) {
    uint32_t a;
    asm("{ .reg .u64 t; cvta.to.shared.u64 t, %1; cvt.u32.u64 %0, t; }" : "=r"(a) : "l"(p));
    return a;
}
__device__ __forceinline__ void cp16(uint32_t s, const void* g) {
    asm volatile("cp.async.cg.shared.global [%0], [%1], 16;" :: "r"(s), "l"(g));
}
__device__ __forceinline__ void cp_commit() { asm volatile("cp.async.commit_group;" ::: "memory"); }
__device__ __forceinline__ void cp_wait0()  { asm volatile("cp.async.wait_group 0;" ::: "memory"); }

// float -> monotone sortable uint
__device__ __forceinline__ unsigned f2k(float f) {
    unsigned u = __float_as_uint(f);
    return u ^ ((u & 0x80000000u) ? 0xFFFFFFFFu : 0x80000000u);
}
// pack two floats' bf16 hi parts and bf16 residual lo parts
__device__ __forceinline__ void split2(float x, float y, uint32_t& hi2, uint32_t& lo2) {
    __nv_bfloat16 hx = __float2bfloat16(x), hy = __float2bfloat16(y);
    float rx = x - __bfloat162float(hx), ry = y - __bfloat162float(hy);
    __nv_bfloat16 lx = __float2bfloat16(rx), ly = __float2bfloat16(ry);
    hi2 = (uint32_t)__bfloat16_as_ushort(hx) | ((uint32_t)__bfloat16_as_ushort(hy) << 16);
    lo2 = (uint32_t)__bfloat16_as_ushort(lx) | ((uint32_t)__bfloat16_as_ushort(ly) << 16);
}

// ---------------- kernel 0: W1 -> bf16 hi/lo transpose, zero hist, L2-warm Wz ----------------
__global__ __launch_bounds__(256) void conv_w1(const float* __restrict__ W1,
                                               const float* __restrict__ Wz) {
    int n = blockIdx.x;
    if (threadIdx.x < 16) g_hist[n * 16 + threadIdx.x] = 0u;
    for (int k = threadIdx.x; k < DIN; k += 256) {
        float v = W1[(size_t)k * DH + n];
        __nv_bfloat16 h = __float2bfloat16(v);
        g_Wthi[n * DIN + k] = h;
        g_Wtlo[n * DIN + k] = __float2bfloat16(v - __bfloat162float(h));
    }
    float acc = 0.f;
    const float* wzb = Wz + (size_t)n * 16 * DH;
    for (int i = threadIdx.x; i < 16 * DH; i += 256) acc += wzb[i];
    __shared__ float red[8];
    #pragma unroll
    for (int off = 16; off; off >>= 1) acc += __shfl_xor_sync(0xffffffffu, acc, off);
    if ((threadIdx.x & 31) == 0) red[threadIdx.x >> 5] = acc;
    __syncthreads();
    if (threadIdx.x == 0) {
        float t = 0.f;
        for (int i = 0; i < 8; i++) t += red[i];
        g_dummy[n] = t;
    }
}

// ---------------- kernel 1: WMMA bf16-split GEMM (8 warps, 32x64 tiles) ----------------
__global__ __launch_bounds__(256, 2) void fused_main_tc(
    const float* __restrict__ input,
    const float* __restrict__ b1, const float* __restrict__ g1, const float* __restrict__ be1,
    const float* __restrict__ Watt1, const float* __restrict__ batt1,
    const float* __restrict__ g2, const float* __restrict__ be2,
    const float* __restrict__ Watt2, const float* __restrict__ batt2)
{
    extern __shared__ char sm[];
    __shared__ float sarr[128];
    __shared__ float zred[4];
    const uint32_t su = smem_u32(sm);
    float*         staf = (float*)(sm + OFF_STA);
    __nv_bfloat16* sAhi = (__nv_bfloat16*)(sm + OFF_AHI);
    __nv_bfloat16* sAlo = (__nv_bfloat16*)(sm + OFF_ALO);

    const int tid = threadIdx.x;
    const int lane = tid & 31, wid = tid >> 5;
    const int wg = wid >> 2;          // 0/1: N half (cols 0..63 / 64..127)
    const int w4 = wid & 3;           // 0..3: M group of 32 rows
    const int m0 = blockIdx.x * 128;

    wmma::fragment<wmma::accumulator, 16, 16, 16, float> fc[2][4];
    #pragma unroll
    for (int i = 0; i < 2; i++)
        #pragma unroll
        for (int j = 0; j < 4; j++) wmma::fill_fragment(fc[i][j], 0.0f);

    // prologue: issue chunk 0 (256 threads)
    {
        #pragma unroll
        for (int j = 0; j < 4; j++) {                 // A stage: 1024 slots
            int t = tid + 256 * j;
            int row = t >> 3, c4 = t & 7;
            cp16(su + OFF_STA + row * 144 + c4 * 16, input + (size_t)(m0 + row) * DIN + c4 * 4);
        }
        #pragma unroll
        for (int j = 0; j < 2; j++) {                 // B: 512 slots each
            int t = tid + 256 * j;
            int row = t >> 2, k8 = (t & 3) << 3;
            cp16(su + OFF_BHI + row * 80 + k8 * 2, g_Wthi + row * DIN + k8);
            cp16(su + OFF_BLO + row * 80 + k8 * 2, g_Wtlo + row * DIN + k8);
        }
        cp_commit();
    }

    const int cvr = tid >> 1, cvc = (tid & 1) << 4;   // convert: 2 thr/row, 16 floats each

    for (int c = 0; c < NITER; c++) {
        cp_wait0();
        __syncthreads();
        // convert STA fp32 -> sAhi/sAlo (16 floats per thread)
        {
            const float* sp = staf + cvr * 36 + cvc;
            #pragma unroll
            for (int q = 0; q < 2; q++) {
                float4 u0 = *(const float4*)(sp + q * 8);
                float4 u1 = *(const float4*)(sp + q * 8 + 4);
                uint4 hi, lo;
                split2(u0.x, u0.y, hi.x, lo.x);
                split2(u0.z, u0.w, hi.y, lo.y);
                split2(u1.x, u1.y, hi.z, lo.z);
                split2(u1.z, u1.w, hi.w, lo.w);
                *(uint4*)(sAhi + cvr * 40 + cvc + q * 8) = hi;
                *(uint4*)(sAlo + cvr * 40 + cvc + q * 8) = lo;
            }
        }
        __syncthreads();
        if (c + 1 < NITER) {             // issue chunk c+1 (overlaps MMA below)
            const int k0 = (c + 1) * KC;
            const uint32_t bbuf = ((c + 1) & 1) * 10240u;
            #pragma unroll
            for (int j = 0; j < 4; j++) {
                int t = tid + 256 * j;
                int row = t >> 3, c4 = t & 7;
                cp16(su + OFF_STA + row * 144 + c4 * 16,
                     input + (size_t)(m0 + row) * DIN + k0 + c4 * 4);
            }
            #pragma unroll
            for (int j = 0; j < 2; j++) {
                int t = tid + 256 * j;
                int row = t >> 2, k8 = (t & 3) << 3;
                cp16(su + OFF_BHI + bbuf + row * 80 + k8 * 2, g_Wthi + row * DIN + k0 + k8);
                cp16(su + OFF_BLO + bbuf + row * 80 + k8 * 2, g_Wtlo + row * DIN + k0 + k8);
            }
            cp_commit();
        }
        // MMA chunk c (2 k-steps of 16); warp tile 32x64
        const __nv_bfloat16* Bhi = (__nv_bfloat16*)(sm + OFF_BHI + (c & 1) * 10240);
        const __nv_bfloat16* Blo = (__nv_bfloat16*)(sm + OFF_BLO + (c & 1) * 10240);
        #pragma unroll
        for (int ks = 0; ks < 2; ks++) {
            wmma::fragment<wmma::matrix_a, 16, 16, 16, __nv_bfloat16, wmma::row_major> fahi0, fahi1, falo0, falo1;
            wmma::load_matrix_sync(fahi0, sAhi + (w4 * 32 + 0)  * 40 + ks * 16, 40);
            wmma::load_matrix_sync(fahi1, sAhi + (w4 * 32 + 16) * 40 + ks * 16, 40);
            wmma::load_matrix_sync(falo0, sAlo + (w4 * 32 + 0)  * 40 + ks * 16, 40);
            wmma::load_matrix_sync(falo1, sAlo + (w4 * 32 + 16) * 40 + ks * 16, 40);
            #pragma unroll
            for (int nf = 0; nf < 4; nf++) {
                wmma::fragment<wmma::matrix_b, 16, 16, 16, __nv_bfloat16, wmma::col_major> fb;
                wmma::load_matrix_sync(fb, Bhi + (wg * 64 + nf * 16) * 40 + ks * 16, 40);
                wmma::mma_sync(fc[0][nf], fahi0, fb, fc[0][nf]);
                wmma::mma_sync(fc[1][nf], fahi1, fb, fc[1][nf]);
                wmma::mma_sync(fc[0][nf], falo0, fb, fc[0][nf]);
                wmma::mma_sync(fc[1][nf], falo1, fb, fc[1][nf]);
                wmma::load_matrix_sync(fb, Blo + (wg * 64 + nf * 16) * 40 + ks * 16, 40);
                wmma::mma_sync(fc[0][nf], fahi0, fb, fc[0][nf]);
                wmma::mma_sync(fc[1][nf], fahi1, fb, fc[1][nf]);
            }
        }
    }
    __syncthreads();   // all MMA done before smem reuse

    // -------- epilogue --------
    float* xsf = (float*)(sm + OFF_XS);
    float* xs  = xsf + wid * (32 * XPITCH);    // this warp's 32x64 tile
    float* W1s = (float*)(sm + OFF_W1S);

    #pragma unroll
    for (int i = 0; i < 2; i++)
        #pragma unroll
        for (int nf = 0; nf < 4; nf++)
            wmma::store_matrix_sync(xs + (i * 16) * XPITCH + nf * 16, fc[i][nf],
                                    XPITCH, wmma::mem_row_major);
    for (int i = tid; i < DH * DA; i += 256) W1s[i] = Watt1[i];
    __syncthreads();

    const float invn = rsqrtf(1.0f + 1e-5f);

    // phase A: BN + ReLU in-place + coalesced g_x store (32 rows x 64 cols per warp)
    {
        int hr  = lane >> 4;
        int cc4 = (lane & 15) << 2;
        int c0  = wg * 64 + cc4;
        float4 b4 = __ldg((const float4*)(b1  + c0));
        float4 g4 = __ldg((const float4*)(g1  + c0));
        float4 e4 = __ldg((const float4*)(be1 + c0));
        float s0 = g4.x * invn, s1 = g4.y * invn, s2 = g4.z * invn, s3 = g4.w * invn;
        #pragma unroll
        for (int it = 0; it < 16; it++) {
            int r = it * 2 + hr;
            float4 a = *(float4*)(xs + r * XPITCH + cc4);
            float4 v;
            v.x = fmaxf((a.x + b4.x) * s0 + e4.x, 0.f);
            v.y = fmaxf((a.y + b4.y) * s1 + e4.y, 0.f);
            v.z = fmaxf((a.z + b4.z) * s2 + e4.z, 0.f);
            v.w = fmaxf((a.w + b4.w) * s3 + e4.w, 0.f);
            *(float4*)(xs + r * XPITCH + cc4) = v;
            *(float4*)(g_x + (size_t)(m0 + w4 * 32 + r) * DH + c0) = v;
        }
    }
    __syncthreads();   // all x in smem before cross-warp h reads

    // phase H: warp wid owns rows wid*16..wid*16+15; lane = h column (0..31)
    {
        const int hr0 = wid * 16;
        // row j (global hr0+j) lives in warp (half*4 + (wid>>1)) at local row (wid&1)*16 + j
        float* xbase = xsf + (wid >> 1) * (32 * XPITCH) + ((wid & 1) * 16) * XPITCH;
        float acc16[16];
        #pragma unroll
        for (int j = 0; j < 16; j++) acc16[j] = 0.f;
        for (int cc = 0; cc < DH; cc++) {
            float wv = W1s[cc * DA + lane];
            const float* xcol = xbase + (cc >> 6) * (4 * 32 * XPITCH) + (cc & 63);
            #pragma unroll
            for (int j = 0; j < 16; j++) acc16[j] += xcol[j * XPITCH] * wv;
        }
        float bt = __ldg(batt1 + lane);
        float gg = __ldg(g2 + lane) * invn;
        float bb = __ldg(be2 + lane);
        float w2 = __ldg(Watt2 + lane);
        float b2v = __ldg(batt2);
        #pragma unroll
        for (int j = 0; j < 16; j++) {
            float hv = tanhf((acc16[j] + bt) * gg + bb);
            float term = hv * w2;
            #pragma unroll
            for (int off = 16; off; off >>= 1)
                term += __shfl_xor_sync(0xffffffffu, term, off);
            if (lane == 0) {
                float sv = term + b2v;
                g_s[m0 + hr0 + j] = sv;
                sarr[hr0 + j] = sv;
            }
        }
    }
    __syncthreads();

    // phase S: histogram + deterministic block Z-partial
    if (tid < 128) {
        float sv = sarr[tid];
        atomicAdd(&g_hist[f2k(sv) >> 21], 1u);
        float e = expf(sv);
        #pragma unroll
        for (int off = 16; off; off >>= 1) e += __shfl_xor_sync(0xffffffffu, e, off);
        if ((tid & 31) == 0) zred[tid >> 5] = e;
    }
    __syncthreads();
    if (tid == 0)
        g_zpart[blockIdx.x] = ((zred[0] + zred[1]) + (zred[2] + zred[3]));
}

// ---------------- kernel 2: Z reduce + exact top-64 (prebuilt hist + survivor refine) ----------------
__global__ __launch_bounds__(1024) void select_topk()
{
    extern __shared__ char sm2[];
    unsigned* hist = (unsigned*)(sm2);
    unsigned* lkey = (unsigned*)(sm2 + 8192);
    int*      lidx = (int*)(sm2 + 8192 + LCAP * 4);
    int*      eqidx = (int*)(sm2 + 8192 + LCAP * 8);
    __shared__ float zp[32];
    __shared__ int sh_b, sh_cnt, sh_lc, sh_ovf, sh_cg, sh_ce;
    __shared__ unsigned selkey[KSEL];
    __shared__ int selidx[KSEL];

    const int tid = threadIdx.x;
    if (tid == 0) { sh_lc = 0; sh_ovf = 0; }

    {   // Z: deterministic fixed-order tree over NBLK partials
        float z = (tid < NBLK) ? g_zpart[tid] : 0.f;
        #pragma unroll
        for (int off = 16; off; off >>= 1) z += __shfl_xor_sync(0xffffffffu, z, off);
        if ((tid & 31) == 0) zp[tid >> 5] = z;
    }
    __syncthreads();
    if (tid == 0) {
        float zz = 0.f;
        for (int i = 0; i < 32; i++) zz += zp[i];
        g_Z = zz;
        int cum = 0, b = 2047;
        for (; b > 0; b--) { if (cum + (int)g_hist[b] >= KSEL) break; cum += (int)g_hist[b]; }
        sh_b = b; sh_cnt = cum;
    }
    __syncthreads();
    int need = KSEL - sh_cnt;
    const unsigned b1 = (unsigned)sh_b;
    unsigned prefix = b1 << 21, mask = 0xFFE00000u;

    for (int i = tid; i < NTOT; i += 1024) {
        unsigned k = f2k(g_s[i]);
        if ((k >> 21) >= b1) {
            int p = atomicAdd(&sh_lc, 1);
            if (p < LCAP) { lkey[p] = k; lidx[p] = i; }
            else sh_ovf = 1;
        }
    }
    __syncthreads();
    const int lc = (sh_lc < LCAP) ? sh_lc : LCAP;
    const bool useList = (sh_ovf == 0);

    #pragma unroll
    for (int p3 = 0; p3 < 3; p3++) {
        const int shift = (p3 == 0) ? 13 : (p3 == 1) ? 5 : 0;
        const unsigned bm = (p3 == 2) ? 31u : 255u;
        __syncthreads();
        if (tid < 256) hist[tid] = 0;
        __syncthreads();
        if (useList) {
            for (int j = tid; j < lc; j += 1024) {
                unsigned k = lkey[j];
                if ((k & mask) == prefix) atomicAdd(&hist[(k >> shift) & bm], 1u);
            }
        } else {
            for (int i = tid; i < NTOT; i += 1024) {
                unsigned k = f2k(g_s[i]);
                if ((k & mask) == prefix) atomicAdd(&hist[(k >> shift) & bm], 1u);
            }
        }
        __syncthreads();
        if (tid == 0) {
            int cum = 0, b = (int)bm;
            for (; b > 0; b--) { if (cum + (int)hist[b] >= need) break; cum += (int)hist[b]; }
            sh_b = b; sh_cnt = cum;
        }
        __syncthreads();
        need -= sh_cnt;
        prefix |= ((unsigned)sh_b) << shift;
        mask |= bm << shift;
    }
    const unsigned T = prefix;
    const int e_need = need;

    if (tid == 0) { sh_cg = 0; sh_ce = 0; }
    __syncthreads();
    if (useList) {
        for (int j = tid; j < lc; j += 1024) {
            unsigned k = lkey[j];
            if (k > T) { int p = atomicAdd(&sh_cg, 1); selkey[p] = k; selidx[p] = lidx[j]; }
            else if (k == T) { int p = atomicAdd(&sh_ce, 1); if (p < EQCAP) eqidx[p] = lidx[j]; }
        }
    } else {
        for (int i = tid; i < NTOT; i += 1024) {
            unsigned k = f2k(g_s[i]);
            if (k > T) { int p = atomicAdd(&sh_cg, 1); selkey[p] = k; selidx[p] = i; }
            else if (k == T) { int p = atomicAdd(&sh_ce, 1); if (p < EQCAP) eqidx[p] = i; }
        }
    }
    __syncthreads();
    if (tid == 0) {
        int cg = sh_cg, ce = sh_ce;
        if (ce <= EQCAP) {
            for (int j = 0; j < e_need; j++) {
                int mn = j;
                for (int q = j + 1; q < ce; q++) if (eqidx[q] < eqidx[mn]) mn = q;
                int t = eqidx[j]; eqidx[j] = eqidx[mn]; eqidx[mn] = t;
            }
        } else {
            int cnt = 0;
            for (int i = 0; i < NTOT && cnt < e_need; i++)
                if (f2k(g_s[i]) == T) eqidx[cnt++] = i;
        }
        for (int j = 0; j < e_need; j++) { selkey[cg + j] = T; selidx[cg + j] = eqidx[j]; }
    }
    __syncthreads();
    if (tid < KSEL) {
        unsigned mk = selkey[tid]; int mi = selidx[tid];
        int rank = 0;
        for (int j = 0; j < KSEL; j++)
            rank += (selkey[j] > mk) || (selkey[j] == mk && selidx[j] < mi);
        g_topidx[rank] = mi;
    }
}

// ---------------- kernel 3a: zs, zq/zk/zv, attention -> zw (all in smem) ----------------
#define TA_ZS   0                        // 64*129 f = 33024
#define TA_WQ   33024                    // 128*36 f = 18432
#define TA_WK   51456
#define TA_WV   69888
#define TA_ZQ   88320                    // 64*33 f = 8448
#define TA_ZK   96768
#define TA_ZV   105216
#define TA_BYTES 113664
__global__ __launch_bounds__(1024) void tail_a(
    const float* __restrict__ Wq, const float* __restrict__ Wk, const float* __restrict__ Wv)
{
    extern __shared__ char sm3[];
    float* zs = (float*)(sm3 + TA_ZS);
    float* wq = (float*)(sm3 + TA_WQ);
    float* wk = (float*)(sm3 + TA_WK);
    float* wv = (float*)(sm3 + TA_WV);
    float* zq = (float*)(sm3 + TA_ZQ);
    float* zk = (float*)(sm3 + TA_ZK);
    float* zv = (float*)(sm3 + TA_ZV);
    __shared__ float aA[KSEL], w[KSEL];
    __shared__ int idx[KSEL];

    const int tid = threadIdx.x;
    const float Zs = g_Z;

    if (tid < KSEL) {
        int id = g_topidx[tid];
        idx[tid] = id;
        aA[tid] = expf(g_s[id]) / Zs;
    }
    for (int i = tid; i < DH * DA; i += 1024) {
        int r = i >> 5, c = i & 31;
        wq[r * 36 + c] = Wq[i];
        wk[r * 36 + c] = Wk[i];
        wv[r * 36 + c] = Wv[i];
    }
    __syncthreads();
    if (tid == 0) {
        float m = aA[0];
        for (int i = 1; i < KSEL; i++) m = fmaxf(m, aA[i]);
        float ssum = 0.f;
        for (int i = 0; i < KSEL; i++) { float e = expf(aA[i] - m); w[i] = e; ssum += e; }
        float rs = 1.0f / ssum;
        for (int i = 0; i < KSEL; i++) w[i] *= rs;
    }
    __syncthreads();
    for (int e = tid; e < KSEL * DH; e += 1024) {
        int i = e >> 7, j = e & 127;
        zs[i * 129 + j] = g_x[(size_t)idx[i] * DH + j] * w[i];
    }
    __syncthreads();
    if (tid < 384) {
        int rg = tid / 24, slot = tid % 24;
        int mat = slot >> 3, c4 = (slot & 7) << 2;
        const float* W = (mat == 0) ? wq : (mat == 1) ? wk : wv;
        float* dst = (mat == 0) ? zq : (mat == 1) ? zk : zv;
        float a0[4], a1[4], a2[4], a3[4];
        #pragma unroll
        for (int c = 0; c < 4; c++) { a0[c] = a1[c] = a2[c] = a3[c] = 0.f; }
        const float* z0 = zs + (rg * 4) * 129;
        for (int kk = 0; kk < DH; kk++) {
            float4 wv4 = *(const float4*)(W + kk * 36 + c4);
            float x0 = z0[kk], x1 = z0[129 + kk], x2 = z0[258 + kk], x3 = z0[387 + kk];
            a0[0] += x0 * wv4.x; a0[1] += x0 * wv4.y; a0[2] += x0 * wv4.z; a0[3] += x0 * wv4.w;
            a1[0] += x1 * wv4.x; a1[1] += x1 * wv4.y; a1[2] += x1 * wv4.z; a1[3] += x1 * wv4.w;
            a2[0] += x2 * wv4.x; a2[1] += x2 * wv4.y; a2[2] += x2 * wv4.z; a2[3] += x2 * wv4.w;
            a3[0] += x3 * wv4.x; a3[1] += x3 * wv4.y; a3[2] += x3 * wv4.z; a3[3] += x3 * wv4.w;
        }
        #pragma unroll
        for (int c = 0; c < 4; c++) {
            dst[(rg * 4 + 0) * 33 + c4 + c] = a0[c];
            dst[(rg * 4 + 1) * 33 + c4 + c] = a1[c];
            dst[(rg * 4 + 2) * 33 + c4 + c] = a2[c];
            dst[(rg * 4 + 3) * 33 + c4 + c] = a3[c];
        }
    }
    __syncthreads();
    {
        int lane = tid & 31, wd = tid >> 5;
        #pragma unroll
        for (int rr = 0; rr < 2; rr++) {
            int i = wd * 2 + rr;
            float l0 = 0, l1 = 0;
            #pragma unroll
            for (int c = 0; c < DA; c++) {
                float qv = zq[i * 33 + c];
                l0 += qv * zk[lane * 33 + c];
                l1 += qv * zk[(lane + 32) * 33 + c];
            }
            float m = fmaxf(l0, l1);
            #pragma unroll
            for (int off = 16; off; off >>= 1)
                m = fmaxf(m, __shfl_xor_sync(0xffffffffu, m, off));
            float p0 = expf(l0 - m), p1 = expf(l1 - m);
            float ss = p0 + p1;
            #pragma unroll
            for (int off = 16; off; off >>= 1) ss += __shfl_xor_sync(0xffffffffu, ss, off);
            float rs = 1.0f / ss;
            p0 *= rs; p1 *= rs;
            float acc = 0.f;
            #pragma unroll
            for (int j = 0; j < 32; j++) {
                float pj = __shfl_sync(0xffffffffu, p0, j);
                acc += pj * zv[j * 33 + lane];
            }
            #pragma unroll
            for (int j = 0; j < 32; j++) {
                float pj = __shfl_sync(0xffffffffu, p1, j);
                acc += pj * zv[(j + 32) * 33 + lane];
            }
            g_zw[i * DA + lane] = acc;
        }
    }
}

// ---------------- kernel 3b: Wz partials (16 blocks) ----------------
__global__ __launch_bounds__(128) void tail_b(const float* __restrict__ Wz)
{
    __shared__ float zws[128];
    const int g = blockIdx.x, n = threadIdx.x;
    const int mb = g * 128;
    zws[n] = g_zw[mb + n];
    __syncthreads();
    float acc = 0.f;
    #pragma unroll 8
    for (int m = 0; m < 128; m++)
        acc += zws[m] * __ldg(Wz + (size_t)(mb + m) * DH + n);
    g_part[g * DH + n] = acc;
}

// ---------------- kernel 3c: reduce + relu + fc ----------------
__global__ __launch_bounds__(128) void tail_c(
    const float* __restrict__ bz, const float* __restrict__ Wf,
    const float* __restrict__ bf, float* __restrict__ out)
{
    __shared__ float red[4];
    const int t = threadIdx.x;
    float a = bz[t];
    #pragma unroll
    for (int g = 0; g < 16; g++) a += g_part[g * DH + t];
    float zv = fmaxf(a, 0.f) * Wf[t];
    #pragma unroll
    for (int off = 16; off; off >>= 1) zv += __shfl_xor_sync(0xffffffffu, zv, off);
    if ((t & 31) == 0) red[t >> 5] = zv;
    __syncthreads();
    if (t == 0) out[0] = red[0] + red[1] + red[2] + red[3] + bf[0];
}

// ---------------- host launcher ----------------
extern "C" void kernel_launch(void* const* d_in, const int* in_sizes, int n_in,
                              void* d_out, int out_size)
{
    const float* input = (const float*)d_in[0];
    const float* W1    = (const float*)d_in[1];
    const float* b1    = (const float*)d_in[2];
    const float* g1    = (const float*)d_in[3];
    const float* be1   = (const float*)d_in[4];
    const float* Watt1 = (const float*)d_in[5];
    const float* batt1 = (const float*)d_in[6];
    const float* g2    = (const float*)d_in[7];
    const float* be2   = (const float*)d_in[8];
    const float* Watt2 = (const float*)d_in[9];
    const float* batt2 = (const float*)d_in[10];
    const float* Wq    = (const float*)d_in[11];
    const float* Wk    = (const float*)d_in[12];
    const float* Wv    = (const float*)d_in[13];
    const float* Wz    = (const float*)d_in[14];
    const float* bz    = (const float*)d_in[15];
    const float* Wf    = (const float*)d_in[16];
    const float* bf    = (const float*)d_in[17];

    static const int SEL_BYTES = 8192 + LCAP * 8 + EQCAP * 4;
    cudaFuncSetAttribute(fused_main_tc, cudaFuncAttributeMaxDynamicSharedMemorySize, SM_BYTES);
    cudaFuncSetAttribute(select_topk,  cudaFuncAttributeMaxDynamicSharedMemorySize, SEL_BYTES);
    cudaFuncSetAttribute(tail_a,       cudaFuncAttributeMaxDynamicSharedMemorySize, TA_BYTES);

    conv_w1<<<DH, 256>>>(W1, Wz);
    fused_main_tc<<<NBLK, 256, SM_BYTES>>>(input, b1, g1, be1,
                                           Watt1, batt1, g2, be2, Watt2, batt2);
    select_topk<<<1, 1024, SEL_BYTES>>>();
    tail_a<<<1, 1024, TA_BYTES>>>(Wq, Wk, Wv);
    tail_b<<<16, 128>>>(Wz);
    tail_c<<<1, 128>>>(bz, Wf, bf, (float*)d_out);
}